// round 14
// baseline (speedup 1.0000x reference)
#include <cuda_runtime.h>
#include <cuda_fp16.h>
#include <math.h>
#include <stdint.h>

#define CC     64
#define C8     8
#define NN     9216
#define BB     2
#define SPLITS 2
#define KPS    (NN / SPLITS)    // 4608 keys per split
#define TK     128              // keys staged per smem tile
#define NT     (KPS / TK)       // 36 tiles per block
#define VPAD   72               // sVh row pitch in halves (144B)
#define KROW   136              // sKh/sKl row pitch in halves (272B)
#define LOG2E  1.44269504088896340736f

// Scratch (no allocations allowed in kernel_launch)
__device__ float        g_sigma[3];
__device__ unsigned int g_kmax2;                   // max ||f_i||^2 (bits of nonneg float)
__device__ __half       g_fh[BB * C8 * NN];        // keys fp16 hi  [B, 8, N]
__device__ __half       g_fl[BB * C8 * NN];        // keys fp16 lo  [B, 8, N]
__device__ float        g_g[BB * C8 * NN];         // queries [B, 8, N] fp32
__device__ __half       g_ht[BB * NN * CC];        // values  [B, N, 64] fp16 (row-major)
__device__ float        g_pl[BB * SPLITS * NN];    // split partial denominators
__device__ float        g_pacc[BB * SPLITS * CC * NN];  // split partial numerators

// ---- packed f32x2 helpers (SASS FFMA2) ----
__device__ __forceinline__ uint64_t pack2(float lo, float hi) {
    uint64_t r; asm("mov.b64 %0, {%1, %2};" : "=l"(r) : "f"(lo), "f"(hi)); return r;
}
__device__ __forceinline__ uint64_t ffma2(uint64_t a, uint64_t b, uint64_t c) {
    uint64_t d; asm("fma.rn.f32x2 %0, %1, %2, %3;" : "=l"(d) : "l"(a), "l"(b), "l"(c)); return d;
}
__device__ __forceinline__ void unpack2(uint64_t v, float& lo, float& hi) {
    asm("mov.b64 {%0, %1}, %2;" : "=f"(lo), "=f"(hi) : "l"(v));
}
__device__ __forceinline__ float ex2(float x) {
    float r; asm("ex2.approx.f32 %0, %1;" : "=f"(r) : "f"(x)); return r;
}
// d = {lo, hi} packed fp16x2 (first asm source -> high half)
__device__ __forceinline__ uint32_t cvt16x2(float hi, float lo) {
    uint32_t d; asm("cvt.rn.f16x2.f32 %0, %1, %2;" : "=r"(d) : "f"(hi), "f"(lo)); return d;
}
__device__ __forceinline__ void mma16816(float& d0, float& d1, float& d2, float& d3,
                                         uint32_t a0, uint32_t a1, uint32_t a2, uint32_t a3,
                                         uint32_t b0, uint32_t b1) {
    asm volatile("mma.sync.aligned.m16n8k16.row.col.f32.f16.f16.f32 "
                 "{%0,%1,%2,%3}, {%4,%5,%6,%7}, {%8,%9}, {%0,%1,%2,%3};"
                 : "+f"(d0), "+f"(d1), "+f"(d2), "+f"(d3)
                 : "r"(a0), "r"(a1), "r"(a2), "r"(a3), "r"(b0), "r"(b1));
}
__device__ __forceinline__ void mma16808(float& d0, float& d1, float& d2, float& d3,
                                         uint32_t a0, uint32_t a1, uint32_t b0) {
    asm volatile("mma.sync.aligned.m16n8k8.row.col.f32.f16.f16.f32 "
                 "{%0,%1,%2,%3}, {%4,%5}, {%6}, {%0,%1,%2,%3};"
                 : "+f"(d0), "+f"(d1), "+f"(d2), "+f"(d3)
                 : "r"(a0), "r"(a1), "r"(b0));
}
__device__ __forceinline__ void ldmx4t(uint32_t& b0, uint32_t& b1, uint32_t& b2, uint32_t& b3,
                                       uint32_t smaddr) {
    asm volatile("ldmatrix.sync.aligned.m8n8.x4.trans.shared.b16 {%0,%1,%2,%3}, [%4];"
                 : "=r"(b0), "=r"(b1), "=r"(b2), "=r"(b3) : "r"(smaddr));
}
__device__ __forceinline__ void ldmx2t(uint32_t& b0, uint32_t& b1, uint32_t smaddr) {
    asm volatile("ldmatrix.sync.aligned.m8n8.x2.trans.shared.b16 {%0,%1}, [%2];"
                 : "=r"(b0), "=r"(b1) : "r"(smaddr));
}
// ---- cp.async (LDGSTS) ----
__device__ __forceinline__ void cpa16(uint32_t dst, const void* src) {
    asm volatile("cp.async.cg.shared.global [%0], [%1], 16;" :: "r"(dst), "l"(src));
}
__device__ __forceinline__ void cpa_commit() {
    asm volatile("cp.async.commit_group;");
}
template <int N>
__device__ __forceinline__ void cpa_wait() {
    asm volatile("cp.async.wait_group %0;" :: "n"(N));
}

// ---------------------------------------------------------------------------
// Kernel 1: spectral norms via power iteration on Gram matrix G = W W^T.
// ---------------------------------------------------------------------------
__global__ __launch_bounds__(64)
void sigma_kernel(const float* __restrict__ Wq,
                  const float* __restrict__ Wk,
                  const float* __restrict__ Wv) {
    __shared__ float sW[64 * 64];
    __shared__ float v[64];
    __shared__ float red[2];
    const int bid = blockIdx.x;
    const int tid = threadIdx.x;
    if (bid == 0 && tid == 0) g_kmax2 = 0u;
    const float* W = (bid == 0) ? Wq : ((bid == 1) ? Wk : Wv);
    const int R = (bid == 2) ? 64 : 8;

    for (int e = tid; e < R * 64; e += 64) sW[e] = W[e];
    if (tid < R) v[tid] = 1.f;
    __syncthreads();

    float Gr[64];
    if (tid < R) {
        uint64_t w2[32];
        const uint64_t* wrp = (const uint64_t*)&sW[tid * 64];
        #pragma unroll
        for (int i = 0; i < 32; i++) w2[i] = wrp[i];
        for (int c = 0; c < R; c++) {
            const uint64_t* wcp = (const uint64_t*)&sW[c * 64];   // broadcast
            uint64_t a0 = 0ull, a1 = 0ull, a2 = 0ull, a3 = 0ull;
            #pragma unroll
            for (int kk = 0; kk < 32; kk += 4) {
                a0 = ffma2(w2[kk],     wcp[kk],     a0);
                a1 = ffma2(w2[kk + 1], wcp[kk + 1], a1);
                a2 = ffma2(w2[kk + 2], wcp[kk + 2], a2);
                a3 = ffma2(w2[kk + 3], wcp[kk + 3], a3);
            }
            float x0, x1, y0, y1, z0, z1, u0, u1;
            unpack2(a0, x0, x1); unpack2(a1, y0, y1);
            unpack2(a2, z0, z1); unpack2(a3, u0, u1);
            Gr[c] = ((x0 + x1) + (y0 + y1)) + ((z0 + z1) + (u0 + u1));
        }
    }
    __syncthreads();

    float lam = 1.f;
    for (int it = 0; it < 56; it++) {
        float s = 0.f;
        if (tid < R) {
            if (R == 8) {
                float2 v0 = *(const float2*)&v[0], v1 = *(const float2*)&v[2];
                float2 v2 = *(const float2*)&v[4], v3 = *(const float2*)&v[6];
                s = ((Gr[0] * v0.x + Gr[1] * v0.y) + (Gr[2] * v1.x + Gr[3] * v1.y))
                  + ((Gr[4] * v2.x + Gr[5] * v2.y) + (Gr[6] * v3.x + Gr[7] * v3.y));
            } else {
                float a0 = 0.f, a1 = 0.f, a2 = 0.f, a3 = 0.f;
                #pragma unroll
                for (int k4 = 0; k4 < 16; k4++) {
                    float4 vv = *(const float4*)&v[k4 * 4];
                    a0 += Gr[k4 * 4]     * vv.x;
                    a1 += Gr[k4 * 4 + 1] * vv.y;
                    a2 += Gr[k4 * 4 + 2] * vv.z;
                    a3 += Gr[k4 * 4 + 3] * vv.w;
                }
                s = (a0 + a1) + (a2 + a3);
            }
        }
        float sq = (tid < R) ? s * s : 0.f;
        #pragma unroll
        for (int off = 16; off > 0; off >>= 1)
            sq += __shfl_xor_sync(0xffffffff, sq, off);
        if ((tid & 31) == 0) red[tid >> 5] = sq;
        __syncthreads();
        float nrm = sqrtf(red[0] + red[1]);
        lam = nrm;                         // ||G v|| -> sigma^2
        if (tid < R) v[tid] = s / nrm;
        __syncthreads();
    }
    if (tid == 0) g_sigma[bid] = sqrtf(lam);
}

// ---------------------------------------------------------------------------
// Kernel 2: projections with FFMA2-packed transposed weights.
// keys -> fp16 hi/lo planes [c][n]; queries fp32 [c][n]; h -> fp16 [n][c].
// ---------------------------------------------------------------------------
__global__ __launch_bounds__(128)
void proj_kernel(const float* __restrict__ x,
                 const float* __restrict__ Wq, const float* __restrict__ bq,
                 const float* __restrict__ Wk, const float* __restrict__ bk,
                 const float* __restrict__ Wv, const float* __restrict__ bv) {
    __shared__ uint64_t sWqP[CC * 4];
    __shared__ uint64_t sWkP[CC * 4];
    __shared__ uint64_t sWvP[CC * 32];
    __shared__ uint64_t sbqP[4], sbkP[4], sbvP[32];
    __shared__ float    swmax[4];

    const int tid = threadIdx.x;
    const float isq = 1.f / g_sigma[0];
    const float isk = 1.f / g_sigma[1];
    const float isv = 1.f / g_sigma[2];

    for (int e = tid; e < CC * 4; e += 128) {
        int k = e >> 2, p = e & 3;
        sWqP[e] = pack2(Wq[(2 * p) * CC + k] * isq, Wq[(2 * p + 1) * CC + k] * isq);
        sWkP[e] = pack2(Wk[(2 * p) * CC + k] * isk, Wk[(2 * p + 1) * CC + k] * isk);
    }
    for (int e = tid; e < CC * 32; e += 128) {
        int k = e >> 5, p = e & 31;
        sWvP[e] = pack2(Wv[(2 * p) * CC + k] * isv, Wv[(2 * p + 1) * CC + k] * isv);
    }
    if (tid < 4)  { sbqP[tid] = pack2(bq[2 * tid], bq[2 * tid + 1]);
                    sbkP[tid] = pack2(bk[2 * tid], bk[2 * tid + 1]); }
    if (tid < 32) { sbvP[tid] = pack2(bv[2 * tid], bv[2 * tid + 1]); }
    __syncthreads();

    const int t = blockIdx.x * 128 + tid;
    const int b = t / NN;
    const int n = t % NN;

    float xr[CC];
    #pragma unroll
    for (int c = 0; c < CC; c++) xr[c] = x[(b * CC + c) * NN + n];

    uint64_t fa[4], ga[4];
    #pragma unroll
    for (int p = 0; p < 4; p++) { fa[p] = sbqP[p]; ga[p] = sbkP[p]; }
    #pragma unroll
    for (int k = 0; k < CC; k++) {
        uint64_t xb = pack2(xr[k], xr[k]);
        const uint64_t* wq = &sWqP[k * 4];
        const uint64_t* wk = &sWkP[k * 4];
        #pragma unroll
        for (int p = 0; p < 4; p++) {
            fa[p] = ffma2(xb, wq[p], fa[p]);
            ga[p] = ffma2(xb, wk[p], ga[p]);
        }
    }
    float nf = 0.f;
    #pragma unroll
    for (int p = 0; p < 4; p++) {
        float f0, f1, g0, g1;
        unpack2(fa[p], f0, f1); unpack2(ga[p], g0, g1);
        const int i0 = (b * C8 + 2 * p) * NN + n;
        const int i1 = (b * C8 + 2 * p + 1) * NN + n;
        __half h0 = __float2half_rn(f0), h1 = __float2half_rn(f1);
        g_fh[i0] = h0;  g_fl[i0] = __float2half_rn(f0 - __half2float(h0));
        g_fh[i1] = h1;  g_fl[i1] = __float2half_rn(f1 - __half2float(h1));
        g_g[i0] = g0;
        g_g[i1] = g1;
        nf += f0 * f0 + f1 * f1;
    }

    float wm = nf;
    #pragma unroll
    for (int off = 16; off > 0; off >>= 1)
        wm = fmaxf(wm, __shfl_xor_sync(0xffffffff, wm, off));
    if ((tid & 31) == 0) swmax[tid >> 5] = wm;
    __syncthreads();
    if (tid == 0) {
        float bm = fmaxf(fmaxf(swmax[0], swmax[1]), fmaxf(swmax[2], swmax[3]));
        atomicMax(&g_kmax2, __float_as_uint(bm));
    }

    uint64_t ha[32];
    #pragma unroll
    for (int p = 0; p < 32; p++) ha[p] = sbvP[p];
    #pragma unroll
    for (int k = 0; k < CC; k++) {
        uint64_t xb = pack2(xr[k], xr[k]);
        const uint64_t* wv = &sWvP[k * 32];
        #pragma unroll
        for (int p = 0; p < 32; p++) ha[p] = ffma2(xb, wv[p], ha[p]);
    }
    uint32_t* ht = (uint32_t*)&g_ht[(b * NN + n) * CC];
    #pragma unroll
    for (int p = 0; p < 32; p++) {
        float h0, h1;
        unpack2(ha[p], h0, h1);
        ht[p] = cvt16x2(h1, h0);
    }
}

// ---------------------------------------------------------------------------
// Kernel 3: full-HMMA flash attention, fixed-M softmax, cp.async pipeline.
// QK per n-group: 1x m16n8k8 (qh.kh) + 1x m16n8k16 (qh.kl + ql.kh, exploiting
// that a k8 B-register is layout-identical to the k16 b1 register).
// occ 5 CTAs/SM (227.8KB smem). grid = (144, B, SPLITS).
// ---------------------------------------------------------------------------
__global__ __launch_bounds__(128, 5)
void attn_kernel() {
    __shared__ __align__(16) __half sKh[2][C8][KROW];   // key hi [stage][c][i]
    __shared__ __align__(16) __half sKl[2][C8][KROW];   // key lo
    __shared__ __align__(16) __half sVh[2][TK][VPAD];   // values [stage][i][c]

    const int b    = blockIdx.y;
    const int sp   = blockIdx.z;
    const int tid  = threadIdx.x;
    const int warp = tid >> 5;
    const int lane = tid & 31;
    const int gid  = lane >> 2, tig = lane & 3;
    const int jt   = blockIdx.x * 64 + warp * 16;
    const int j0   = jt + gid, j1 = j0 + 8;

    // queries + fixed per-row log2-domain bound M (Cauchy-Schwarz)
    float q0[C8], q1[C8];
    float nq0 = 0.f, nq1 = 0.f;
    #pragma unroll
    for (int c = 0; c < C8; c++) {
        q0[c] = g_g[(b * C8 + c) * NN + j0]; nq0 += q0[c] * q0[c];
        q1[c] = g_g[(b * C8 + c) * NN + j1]; nq1 += q1[c] * q1[c];
    }
    const float kmax = sqrtf(__uint_as_float(g_kmax2));
    const float M0 = sqrtf(nq0) * kmax * LOG2E - 10.f;
    const float M1 = sqrtf(nq1) * kmax * LOG2E - 10.f;

    // Q A-fragments (k = channels 2*tig, 2*tig+1), hi/lo split
    const int c0 = 2 * tig, c1 = c0 + 1;
    const float qs00 = q0[c0] * LOG2E, qs01 = q0[c1] * LOG2E;
    const float qs10 = q1[c0] * LOG2E, qs11 = q1[c1] * LOG2E;
    const uint32_t aqh0 = cvt16x2(qs01, qs00);         // row j0
    const uint32_t aqh1 = cvt16x2(qs11, qs10);         // row j1
    __half2 hq0 = *(const __half2*)&aqh0;
    __half2 hq1 = *(const __half2*)&aqh1;
    const uint32_t aql0 = cvt16x2(qs01 - __high2float(hq0), qs00 - __low2float(hq0));
    const uint32_t aql1 = cvt16x2(qs11 - __high2float(hq1), qs10 - __low2float(hq1));

    float acc[32];
    #pragma unroll
    for (int c = 0; c < 32; c++) acc[c] = 0.f;
    float l0 = 0.f, l1 = 0.f;

    const uint32_t skh_base = (uint32_t)__cvta_generic_to_shared(&sKh[0][0][0]);
    const uint32_t skl_base = (uint32_t)__cvta_generic_to_shared(&sKl[0][0][0]);
    const uint32_t svh_base = (uint32_t)__cvta_generic_to_shared(&sVh[0][0][0]);
    const int lrow = (lane & 7) + ((lane >> 3) & 1) * 8;   // V ldmatrix row
    const int lcol = (lane >> 4) * 8;                      // V ldmatrix col
    const int kal  = lane & 7;                             // K ldmatrix: channel row
    const int kgrp = (lane >> 3) & 1;                      // K ldmatrix: n-group

    const int i_beg = sp * KPS;

    auto prefetch = [&](int tt, int s) {
        const int i0 = i_beg + tt * TK;
        {   // K hi/lo: 8 rows x 16 chunks of 16B each (128 threads exactly)
            int c = tid >> 4, w = tid & 15;
            cpa16(skh_base + (uint32_t)(((s * C8 + c) * KROW + w * 8) * 2),
                  &g_fh[(b * C8 + c) * NN + i0 + w * 8]);
            cpa16(skl_base + (uint32_t)(((s * C8 + c) * KROW + w * 8) * 2),
                  &g_fl[(b * C8 + c) * NN + i0 + w * 8]);
        }
        const __half* vsrc = &g_ht[(b * NN + i0 + tid) * CC];
        const uint32_t vdst = svh_base + (uint32_t)(((s * TK + tid) * VPAD) * 2);
        #pragma unroll
        for (int r = 0; r < 8; r++)
            cpa16(vdst + (uint32_t)(r * 16), vsrc + r * 8);
    };

    prefetch(0, 0);
    cpa_commit();

    for (int tt = 0; tt < NT; tt++) {
        const int s = tt & 1;
        cpa_wait<0>();
        __syncthreads();    // publishes stage s; orders reuse of the other stage
        if (tt + 1 < NT) {
            prefetch(tt + 1, s ^ 1);
            cpa_commit();
        }

        const uint32_t skh_s = skh_base + (uint32_t)(s * C8 * KROW * 2);
        const uint32_t skl_s = skl_base + (uint32_t)(s * C8 * KROW * 2);
        const uint32_t svh_s = svh_base + (uint32_t)(s * TK * VPAD * 2);

        for (int t = 0; t < TK; t += 16) {
            // ---- K B-fragments (hi & lo), 2 n-groups each ----
            const uint32_t koff = (uint32_t)((kal * KROW + t + kgrp * 8) * 2);
            uint32_t kh0, kh1, kl0, kl1;
            ldmx2t(kh0, kh1, skh_s + koff);
            ldmx2t(kl0, kl1, skl_s + koff);
            // ---- scores: hi k8 + combined-residual k16, -M pre-seeded ----
            float dA0 = -M0, dA1 = -M0, dA2 = -M1, dA3 = -M1;
            float dB0 = -M0, dB1 = -M0, dB2 = -M1, dB3 = -M1;
            mma16808(dA0, dA1, dA2, dA3, aqh0, aqh1, kh0);
            mma16808(dB0, dB1, dB2, dB3, aqh0, aqh1, kh1);
            mma16816(dA0, dA1, dA2, dA3, aqh0, aqh1, aql0, aql1, kl0, kh0);
            mma16816(dB0, dB1, dB2, dB3, aqh0, aqh1, aql0, aql1, kl1, kh1);
            // ---- p = 2^(s-M) ----
            float p00 = ex2(dA0), p01 = ex2(dA1), p10 = ex2(dA2), p11 = ex2(dA3);
            float p02 = ex2(dB0), p03 = ex2(dB1), p12 = ex2(dB2), p13 = ex2(dB3);
            l0 += (p00 + p01) + (p02 + p03);
            l1 += (p10 + p11) + (p12 + p13);
            uint32_t a0 = cvt16x2(p01, p00);
            uint32_t a1 = cvt16x2(p11, p10);
            uint32_t a2 = cvt16x2(p03, p02);
            uint32_t a3 = cvt16x2(p13, p12);
            // ---- V fragments + PV MMAs ----
            uint32_t rowaddr = svh_s + (uint32_t)((t + lrow) * (VPAD * 2) + lcol * 2);
            #pragma unroll
            for (int g = 0; g < 4; g++) {
                uint32_t b0, b1, b2, b3;
                ldmx4t(b0, b1, b2, b3, rowaddr + (uint32_t)(g * 32));
                float* d = &acc[g * 8];
                mma16816(d[0], d[1], d[2], d[3], a0, a1, a2, a3, b0, b1);
                mma16816(d[4], d[5], d[6], d[7], a0, a1, a2, a3, b2, b3);
            }
        }
    }

    l0 += __shfl_xor_sync(0xffffffff, l0, 1);
    l0 += __shfl_xor_sync(0xffffffff, l0, 2);
    l1 += __shfl_xor_sync(0xffffffff, l1, 1);
    l1 += __shfl_xor_sync(0xffffffff, l1, 2);

    const int ps = b * SPLITS + sp;
    if (tig == 0) {
        g_pl[ps * NN + j0] = l0;
        g_pl[ps * NN + j1] = l1;
    }
    #pragma unroll
    for (int nt = 0; nt < 8; nt++) {
        const int c = nt * 8 + 2 * tig;
        g_pacc[(ps * CC + c)     * NN + j0] = acc[nt * 4 + 0];
        g_pacc[(ps * CC + c + 1) * NN + j0] = acc[nt * 4 + 1];
        g_pacc[(ps * CC + c)     * NN + j1] = acc[nt * 4 + 2];
        g_pacc[(ps * CC + c + 1) * NN + j1] = acc[nt * 4 + 3];
    }
}

// ---------------------------------------------------------------------------
// Kernel 4: combine split partials (plain sums), residual. grid (72, 16).
// ---------------------------------------------------------------------------
__global__ __launch_bounds__(256)
void reduce_kernel(const float* __restrict__ x,
                   const float* __restrict__ gamma,
                   float* __restrict__ out) {
    const int t  = blockIdx.x * 256 + threadIdx.x;
    const int b  = t / NN;
    const int j  = t % NN;
    const int c0 = blockIdx.y * 4;

    float L = 0.f;
    #pragma unroll
    for (int s = 0; s < SPLITS; s++) L += g_pl[(b * SPLITS + s) * NN + j];
    const float inv = gamma[0] / L;

    #pragma unroll
    for (int c = c0; c < c0 + 4; c++) {
        float a = 0.f;
        #pragma unroll
        for (int s = 0; s < SPLITS; s++)
            a += g_pacc[((b * SPLITS + s) * CC + c) * NN + j];
        const int idx = (b * CC + c) * NN + j;
        out[idx] = a * inv + x[idx];
    }
}

// ---------------------------------------------------------------------------
extern "C" void kernel_launch(void* const* d_in, const int* in_sizes, int n_in,
                              void* d_out, int out_size) {
    const float* x     = (const float*)d_in[0];
    const float* Wq    = (const float*)d_in[1];
    const float* bq    = (const float*)d_in[2];
    const float* Wk    = (const float*)d_in[3];
    const float* bk    = (const float*)d_in[4];
    const float* Wv    = (const float*)d_in[5];
    const float* bv    = (const float*)d_in[6];
    const float* gamma = (const float*)d_in[7];
    float* out = (float*)d_out;

    // maximize shared carveout so 5 CTAs (227.8KB) fit per SM (idempotent,
    // host-side attribute set — not a stream op, graph-capture safe)
    static bool configured = false;
    if (!configured) {
        cudaFuncSetAttribute(attn_kernel,
                             cudaFuncAttributePreferredSharedMemoryCarveout,
                             cudaSharedmemCarveoutMaxShared);
        configured = true;
    }

    sigma_kernel<<<3, 64>>>(Wq, Wk, Wv);
    proj_kernel<<<(BB * NN) / 128, 128>>>(x, Wq, bq, Wk, bk, Wv, bv);
    attn_kernel<<<dim3(NN / 64, BB, SPLITS), 128>>>();
    reduce_kernel<<<dim3((BB * NN) / 256, 16), 256>>>(x, gamma, out);
}

// round 16
// speedup vs baseline: 1.2168x; 1.2168x over previous
#include <cuda_runtime.h>
#include <cuda_fp16.h>
#include <math.h>
#include <stdint.h>

#define CC     64
#define C8     8
#define NN     9216
#define BB     2
#define SPLITS 3
#define KPS    (NN / SPLITS)    // 3072 keys per split
#define TK     128              // keys staged per smem tile
#define NT     (KPS / TK)       // 24 tiles per block
#define VPAD   72               // sVh row pitch in halves (144B)
#define KROW   136              // sKh/sKl row pitch in halves (272B)
#define LOG2E  1.44269504088896340736f

// Scratch (no allocations allowed in kernel_launch)
__device__ float        g_sigma[3];
__device__ unsigned int g_kmax2;                   // max ||f_i||^2 (bits of nonneg float)
__device__ __half       g_fh[BB * C8 * NN];        // keys fp16 hi  [B, 8, N]
__device__ __half       g_fl[BB * C8 * NN];        // keys fp16 lo  [B, 8, N]
__device__ float        g_g[BB * C8 * NN];         // queries [B, 8, N] fp32
__device__ __half       g_ht[BB * NN * CC];        // values  [B, N, 64] fp16 (row-major)
__device__ float        g_pl[BB * SPLITS * NN];    // split partial denominators
__device__ float        g_pacc[BB * SPLITS * CC * NN];  // split partial numerators

// ---- packed f32x2 helpers (SASS FFMA2) ----
__device__ __forceinline__ uint64_t pack2(float lo, float hi) {
    uint64_t r; asm("mov.b64 %0, {%1, %2};" : "=l"(r) : "f"(lo), "f"(hi)); return r;
}
__device__ __forceinline__ uint64_t ffma2(uint64_t a, uint64_t b, uint64_t c) {
    uint64_t d; asm("fma.rn.f32x2 %0, %1, %2, %3;" : "=l"(d) : "l"(a), "l"(b), "l"(c)); return d;
}
__device__ __forceinline__ void unpack2(uint64_t v, float& lo, float& hi) {
    asm("mov.b64 {%0, %1}, %2;" : "=f"(lo), "=f"(hi) : "l"(v));
}
__device__ __forceinline__ float ex2(float x) {
    float r; asm("ex2.approx.f32 %0, %1;" : "=f"(r) : "f"(x)); return r;
}
// d = {lo, hi} packed fp16x2 (first asm source -> high half)
__device__ __forceinline__ uint32_t cvt16x2(float hi, float lo) {
    uint32_t d; asm("cvt.rn.f16x2.f32 %0, %1, %2;" : "=r"(d) : "f"(hi), "f"(lo)); return d;
}
__device__ __forceinline__ void mma16816(float& d0, float& d1, float& d2, float& d3,
                                         uint32_t a0, uint32_t a1, uint32_t a2, uint32_t a3,
                                         uint32_t b0, uint32_t b1) {
    asm volatile("mma.sync.aligned.m16n8k16.row.col.f32.f16.f16.f32 "
                 "{%0,%1,%2,%3}, {%4,%5,%6,%7}, {%8,%9}, {%0,%1,%2,%3};"
                 : "+f"(d0), "+f"(d1), "+f"(d2), "+f"(d3)
                 : "r"(a0), "r"(a1), "r"(a2), "r"(a3), "r"(b0), "r"(b1));
}
__device__ __forceinline__ void mma16808(float& d0, float& d1, float& d2, float& d3,
                                         uint32_t a0, uint32_t a1, uint32_t b0) {
    asm volatile("mma.sync.aligned.m16n8k8.row.col.f32.f16.f16.f32 "
                 "{%0,%1,%2,%3}, {%4,%5}, {%6}, {%0,%1,%2,%3};"
                 : "+f"(d0), "+f"(d1), "+f"(d2), "+f"(d3)
                 : "r"(a0), "r"(a1), "r"(b0));
}
__device__ __forceinline__ void ldmx4t(uint32_t& b0, uint32_t& b1, uint32_t& b2, uint32_t& b3,
                                       uint32_t smaddr) {
    asm volatile("ldmatrix.sync.aligned.m8n8.x4.trans.shared.b16 {%0,%1,%2,%3}, [%4];"
                 : "=r"(b0), "=r"(b1), "=r"(b2), "=r"(b3) : "r"(smaddr));
}
__device__ __forceinline__ void ldmx2t(uint32_t& b0, uint32_t& b1, uint32_t smaddr) {
    asm volatile("ldmatrix.sync.aligned.m8n8.x2.trans.shared.b16 {%0,%1}, [%2];"
                 : "=r"(b0), "=r"(b1) : "r"(smaddr));
}
// ---- cp.async (LDGSTS) ----
__device__ __forceinline__ void cpa16(uint32_t dst, const void* src) {
    asm volatile("cp.async.cg.shared.global [%0], [%1], 16;" :: "r"(dst), "l"(src));
}
__device__ __forceinline__ void cpa_commit() {
    asm volatile("cp.async.commit_group;");
}
template <int N>
__device__ __forceinline__ void cpa_wait() {
    asm volatile("cp.async.wait_group %0;" :: "n"(N));
}

// ---------------------------------------------------------------------------
// Kernel 1: spectral norms via power iteration on Gram matrix G = W W^T.
// ---------------------------------------------------------------------------
__global__ __launch_bounds__(64)
void sigma_kernel(const float* __restrict__ Wq,
                  const float* __restrict__ Wk,
                  const float* __restrict__ Wv) {
    __shared__ float sW[64 * 64];
    __shared__ float v[64];
    __shared__ float red[2];
    const int bid = blockIdx.x;
    const int tid = threadIdx.x;
    if (bid == 0 && tid == 0) g_kmax2 = 0u;
    const float* W = (bid == 0) ? Wq : ((bid == 1) ? Wk : Wv);
    const int R = (bid == 2) ? 64 : 8;

    for (int e = tid; e < R * 64; e += 64) sW[e] = W[e];
    if (tid < R) v[tid] = 1.f;
    __syncthreads();

    float Gr[64];
    if (tid < R) {
        uint64_t w2[32];
        const uint64_t* wrp = (const uint64_t*)&sW[tid * 64];
        #pragma unroll
        for (int i = 0; i < 32; i++) w2[i] = wrp[i];
        for (int c = 0; c < R; c++) {
            const uint64_t* wcp = (const uint64_t*)&sW[c * 64];   // broadcast
            uint64_t a0 = 0ull, a1 = 0ull, a2 = 0ull, a3 = 0ull;
            #pragma unroll
            for (int kk = 0; kk < 32; kk += 4) {
                a0 = ffma2(w2[kk],     wcp[kk],     a0);
                a1 = ffma2(w2[kk + 1], wcp[kk + 1], a1);
                a2 = ffma2(w2[kk + 2], wcp[kk + 2], a2);
                a3 = ffma2(w2[kk + 3], wcp[kk + 3], a3);
            }
            float x0, x1, y0, y1, z0, z1, u0, u1;
            unpack2(a0, x0, x1); unpack2(a1, y0, y1);
            unpack2(a2, z0, z1); unpack2(a3, u0, u1);
            Gr[c] = ((x0 + x1) + (y0 + y1)) + ((z0 + z1) + (u0 + u1));
        }
    }
    __syncthreads();

    float lam = 1.f;
    for (int it = 0; it < 56; it++) {
        float s = 0.f;
        if (tid < R) {
            if (R == 8) {
                float2 v0 = *(const float2*)&v[0], v1 = *(const float2*)&v[2];
                float2 v2 = *(const float2*)&v[4], v3 = *(const float2*)&v[6];
                s = ((Gr[0] * v0.x + Gr[1] * v0.y) + (Gr[2] * v1.x + Gr[3] * v1.y))
                  + ((Gr[4] * v2.x + Gr[5] * v2.y) + (Gr[6] * v3.x + Gr[7] * v3.y));
            } else {
                float a0 = 0.f, a1 = 0.f, a2 = 0.f, a3 = 0.f;
                #pragma unroll
                for (int k4 = 0; k4 < 16; k4++) {
                    float4 vv = *(const float4*)&v[k4 * 4];
                    a0 += Gr[k4 * 4]     * vv.x;
                    a1 += Gr[k4 * 4 + 1] * vv.y;
                    a2 += Gr[k4 * 4 + 2] * vv.z;
                    a3 += Gr[k4 * 4 + 3] * vv.w;
                }
                s = (a0 + a1) + (a2 + a3);
            }
        }
        float sq = (tid < R) ? s * s : 0.f;
        #pragma unroll
        for (int off = 16; off > 0; off >>= 1)
            sq += __shfl_xor_sync(0xffffffff, sq, off);
        if ((tid & 31) == 0) red[tid >> 5] = sq;
        __syncthreads();
        float nrm = sqrtf(red[0] + red[1]);
        lam = nrm;                         // ||G v|| -> sigma^2
        if (tid < R) v[tid] = s / nrm;
        __syncthreads();
    }
    if (tid == 0) g_sigma[bid] = sqrtf(lam);
}

// ---------------------------------------------------------------------------
// Kernel 2: projections with FFMA2-packed transposed weights.
// keys -> fp16 hi/lo planes [c][n]; queries fp32 [c][n]; h -> fp16 [n][c].
// ---------------------------------------------------------------------------
__global__ __launch_bounds__(128)
void proj_kernel(const float* __restrict__ x,
                 const float* __restrict__ Wq, const float* __restrict__ bq,
                 const float* __restrict__ Wk, const float* __restrict__ bk,
                 const float* __restrict__ Wv, const float* __restrict__ bv) {
    __shared__ uint64_t sWqP[CC * 4];
    __shared__ uint64_t sWkP[CC * 4];
    __shared__ uint64_t sWvP[CC * 32];
    __shared__ uint64_t sbqP[4], sbkP[4], sbvP[32];
    __shared__ float    swmax[4];

    const int tid = threadIdx.x;
    const float isq = 1.f / g_sigma[0];
    const float isk = 1.f / g_sigma[1];
    const float isv = 1.f / g_sigma[2];

    for (int e = tid; e < CC * 4; e += 128) {
        int k = e >> 2, p = e & 3;
        sWqP[e] = pack2(Wq[(2 * p) * CC + k] * isq, Wq[(2 * p + 1) * CC + k] * isq);
        sWkP[e] = pack2(Wk[(2 * p) * CC + k] * isk, Wk[(2 * p + 1) * CC + k] * isk);
    }
    for (int e = tid; e < CC * 32; e += 128) {
        int k = e >> 5, p = e & 31;
        sWvP[e] = pack2(Wv[(2 * p) * CC + k] * isv, Wv[(2 * p + 1) * CC + k] * isv);
    }
    if (tid < 4)  { sbqP[tid] = pack2(bq[2 * tid], bq[2 * tid + 1]);
                    sbkP[tid] = pack2(bk[2 * tid], bk[2 * tid + 1]); }
    if (tid < 32) { sbvP[tid] = pack2(bv[2 * tid], bv[2 * tid + 1]); }
    __syncthreads();

    const int t = blockIdx.x * 128 + tid;
    const int b = t / NN;
    const int n = t % NN;

    float xr[CC];
    #pragma unroll
    for (int c = 0; c < CC; c++) xr[c] = x[(b * CC + c) * NN + n];

    uint64_t fa[4], ga[4];
    #pragma unroll
    for (int p = 0; p < 4; p++) { fa[p] = sbqP[p]; ga[p] = sbkP[p]; }
    #pragma unroll
    for (int k = 0; k < CC; k++) {
        uint64_t xb = pack2(xr[k], xr[k]);
        const uint64_t* wq = &sWqP[k * 4];
        const uint64_t* wk = &sWkP[k * 4];
        #pragma unroll
        for (int p = 0; p < 4; p++) {
            fa[p] = ffma2(xb, wq[p], fa[p]);
            ga[p] = ffma2(xb, wk[p], ga[p]);
        }
    }
    float nf = 0.f;
    #pragma unroll
    for (int p = 0; p < 4; p++) {
        float f0, f1, g0, g1;
        unpack2(fa[p], f0, f1); unpack2(ga[p], g0, g1);
        const int i0 = (b * C8 + 2 * p) * NN + n;
        const int i1 = (b * C8 + 2 * p + 1) * NN + n;
        __half h0 = __float2half_rn(f0), h1 = __float2half_rn(f1);
        g_fh[i0] = h0;  g_fl[i0] = __float2half_rn(f0 - __half2float(h0));
        g_fh[i1] = h1;  g_fl[i1] = __float2half_rn(f1 - __half2float(h1));
        g_g[i0] = g0;
        g_g[i1] = g1;
        nf += f0 * f0 + f1 * f1;
    }

    float wm = nf;
    #pragma unroll
    for (int off = 16; off > 0; off >>= 1)
        wm = fmaxf(wm, __shfl_xor_sync(0xffffffff, wm, off));
    if ((tid & 31) == 0) swmax[tid >> 5] = wm;
    __syncthreads();
    if (tid == 0) {
        float bm = fmaxf(fmaxf(swmax[0], swmax[1]), fmaxf(swmax[2], swmax[3]));
        atomicMax(&g_kmax2, __float_as_uint(bm));
    }

    uint64_t ha[32];
    #pragma unroll
    for (int p = 0; p < 32; p++) ha[p] = sbvP[p];
    #pragma unroll
    for (int k = 0; k < CC; k++) {
        uint64_t xb = pack2(xr[k], xr[k]);
        const uint64_t* wv = &sWvP[k * 32];
        #pragma unroll
        for (int p = 0; p < 32; p++) ha[p] = ffma2(xb, wv[p], ha[p]);
    }
    uint32_t* ht = (uint32_t*)&g_ht[(b * NN + n) * CC];
    #pragma unroll
    for (int p = 0; p < 32; p++) {
        float h0, h1;
        unpack2(ha[p], h0, h1);
        ht[p] = cvt16x2(h1, h0);
    }
}

// ---------------------------------------------------------------------------
// Kernel 3: full-HMMA flash attention, fixed-M softmax, cp.async pipeline.
// Each warp owns TWO 16-j tiles (32 j) sharing K and V fragments: 2x
// intra-warp ILP, half the ldmatrix traffic per j. Block = 128 j.
// grid = (72, B, SPLITS=3) = 432 CTAs, occ 3.
// ---------------------------------------------------------------------------
__global__ __launch_bounds__(128, 3)
void attn_kernel() {
    __shared__ __align__(16) __half sKh[2][C8][KROW];   // key hi [stage][c][i]
    __shared__ __align__(16) __half sKl[2][C8][KROW];   // key lo
    __shared__ __align__(16) __half sVh[2][TK][VPAD];   // values [stage][i][c]

    const int b    = blockIdx.y;
    const int sp   = blockIdx.z;
    const int tid  = threadIdx.x;
    const int warp = tid >> 5;
    const int lane = tid & 31;
    const int gid  = lane >> 2, tig = lane & 3;
    const int jt   = blockIdx.x * 128 + warp * 32;
    const int j0 = jt + gid, j1 = j0 + 8, j2 = j0 + 16, j3 = j0 + 24;

    // queries + fixed per-row log2-domain bound M (Cauchy-Schwarz)
    float qv[4][C8];
    float Mv[4];
    const float kmax = sqrtf(__uint_as_float(g_kmax2));
    const int jr[4] = {j0, j1, j2, j3};
    #pragma unroll
    for (int r = 0; r < 4; r++) {
        float nq = 0.f;
        #pragma unroll
        for (int c = 0; c < C8; c++) {
            qv[r][c] = g_g[(b * C8 + c) * NN + jr[r]];
            nq += qv[r][c] * qv[r][c];
        }
        Mv[r] = sqrtf(nq) * kmax * LOG2E - 10.f;
    }

    // Q A-fragments (k = channels 2*tig, 2*tig+1), hi/lo split, per j-pair
    const int c0 = 2 * tig, c1 = c0 + 1;
    uint32_t aqh[4], aql[4];   // [0],[1]: tile0 rows j0,j1; [2],[3]: tile1 rows j2,j3
    #pragma unroll
    for (int r = 0; r < 4; r++) {
        float s0 = qv[r][c0] * LOG2E, s1 = qv[r][c1] * LOG2E;
        aqh[r] = cvt16x2(s1, s0);
        __half2 hh = *(const __half2*)&aqh[r];
        aql[r] = cvt16x2(s1 - __high2float(hh), s0 - __low2float(hh));
    }

    float accA[32], accB[32];
    #pragma unroll
    for (int c = 0; c < 32; c++) { accA[c] = 0.f; accB[c] = 0.f; }
    float lv[4] = {0.f, 0.f, 0.f, 0.f};

    const uint32_t skh_base = (uint32_t)__cvta_generic_to_shared(&sKh[0][0][0]);
    const uint32_t skl_base = (uint32_t)__cvta_generic_to_shared(&sKl[0][0][0]);
    const uint32_t svh_base = (uint32_t)__cvta_generic_to_shared(&sVh[0][0][0]);
    const int lrow = (lane & 7) + ((lane >> 3) & 1) * 8;   // V ldmatrix row
    const int lcol = (lane >> 4) * 8;                      // V ldmatrix col
    const int kal  = lane & 7;                             // K ldmatrix: channel row
    const int kgrp = (lane >> 3) & 1;                      // K ldmatrix: n-group

    const int i_beg = sp * KPS;

    auto prefetch = [&](int tt, int s) {
        const int i0 = i_beg + tt * TK;
        {   // K hi/lo: 8 rows x 16 chunks of 16B each (128 threads exactly)
            int c = tid >> 4, w = tid & 15;
            cpa16(skh_base + (uint32_t)(((s * C8 + c) * KROW + w * 8) * 2),
                  &g_fh[(b * C8 + c) * NN + i0 + w * 8]);
            cpa16(skl_base + (uint32_t)(((s * C8 + c) * KROW + w * 8) * 2),
                  &g_fl[(b * C8 + c) * NN + i0 + w * 8]);
        }
        const __half* vsrc = &g_ht[(b * NN + i0 + tid) * CC];
        const uint32_t vdst = svh_base + (uint32_t)(((s * TK + tid) * VPAD) * 2);
        #pragma unroll
        for (int r = 0; r < 8; r++)
            cpa16(vdst + (uint32_t)(r * 16), vsrc + r * 8);
    };

    prefetch(0, 0);
    cpa_commit();

    for (int tt = 0; tt < NT; tt++) {
        const int s = tt & 1;
        cpa_wait<0>();
        __syncthreads();    // publishes stage s; orders reuse of the other stage
        if (tt + 1 < NT) {
            prefetch(tt + 1, s ^ 1);
            cpa_commit();
        }

        const uint32_t skh_s = skh_base + (uint32_t)(s * C8 * KROW * 2);
        const uint32_t skl_s = skl_base + (uint32_t)(s * C8 * KROW * 2);
        const uint32_t svh_s = svh_base + (uint32_t)(s * TK * VPAD * 2);

        for (int t = 0; t < TK; t += 16) {
            // ---- K B-fragments (hi & lo), 2 n-groups, shared by both tiles ----
            const uint32_t koff = (uint32_t)((kal * KROW + t + kgrp * 8) * 2);
            uint32_t kh0, kh1, kl0, kl1;
            ldmx2t(kh0, kh1, skh_s + koff);
            ldmx2t(kl0, kl1, skl_s + koff);

            // ---- tile0 scores ----
            float dA0 = -Mv[0], dA1 = -Mv[0], dA2 = -Mv[1], dA3 = -Mv[1];
            float dB0 = -Mv[0], dB1 = -Mv[0], dB2 = -Mv[1], dB3 = -Mv[1];
            mma16808(dA0, dA1, dA2, dA3, aqh[0], aqh[1], kh0);
            mma16808(dB0, dB1, dB2, dB3, aqh[0], aqh[1], kh1);
            mma16816(dA0, dA1, dA2, dA3, aqh[0], aqh[1], aql[0], aql[1], kl0, kh0);
            mma16816(dB0, dB1, dB2, dB3, aqh[0], aqh[1], aql[0], aql[1], kl1, kh1);
            // ---- tile1 scores (independent chain) ----
            float dC0 = -Mv[2], dC1 = -Mv[2], dC2 = -Mv[3], dC3 = -Mv[3];
            float dD0 = -Mv[2], dD1 = -Mv[2], dD2 = -Mv[3], dD3 = -Mv[3];
            mma16808(dC0, dC1, dC2, dC3, aqh[2], aqh[3], kh0);
            mma16808(dD0, dD1, dD2, dD3, aqh[2], aqh[3], kh1);
            mma16816(dC0, dC1, dC2, dC3, aqh[2], aqh[3], aql[2], aql[3], kl0, kh0);
            mma16816(dD0, dD1, dD2, dD3, aqh[2], aqh[3], aql[2], aql[3], kl1, kh1);

            // ---- p = 2^(s-M), 16 independent MUFUs ----
            float p00 = ex2(dA0), p01 = ex2(dA1), p10 = ex2(dA2), p11 = ex2(dA3);
            float p02 = ex2(dB0), p03 = ex2(dB1), p12 = ex2(dB2), p13 = ex2(dB3);
            float p20 = ex2(dC0), p21 = ex2(dC1), p30 = ex2(dC2), p31 = ex2(dC3);
            float p22 = ex2(dD0), p23 = ex2(dD1), p32 = ex2(dD2), p33 = ex2(dD3);
            lv[0] += (p00 + p01) + (p02 + p03);
            lv[1] += (p10 + p11) + (p12 + p13);
            lv[2] += (p20 + p21) + (p22 + p23);
            lv[3] += (p30 + p31) + (p32 + p33);
            uint32_t a0 = cvt16x2(p01, p00);
            uint32_t a1 = cvt16x2(p11, p10);
            uint32_t a2 = cvt16x2(p03, p02);
            uint32_t a3 = cvt16x2(p13, p12);
            uint32_t a4 = cvt16x2(p21, p20);
            uint32_t a5 = cvt16x2(p31, p30);
            uint32_t a6 = cvt16x2(p23, p22);
            uint32_t a7 = cvt16x2(p33, p32);

            // ---- V fragments (shared) + PV MMAs for both tiles ----
            uint32_t rowaddr = svh_s + (uint32_t)((t + lrow) * (VPAD * 2) + lcol * 2);
            #pragma unroll
            for (int g = 0; g < 4; g++) {
                uint32_t b0, b1, b2, b3;
                ldmx4t(b0, b1, b2, b3, rowaddr + (uint32_t)(g * 32));
                float* dA = &accA[g * 8];
                float* dB = &accB[g * 8];
                mma16816(dA[0], dA[1], dA[2], dA[3], a0, a1, a2, a3, b0, b1);
                mma16816(dA[4], dA[5], dA[6], dA[7], a0, a1, a2, a3, b2, b3);
                mma16816(dB[0], dB[1], dB[2], dB[3], a4, a5, a6, a7, b0, b1);
                mma16816(dB[4], dB[5], dB[6], dB[7], a4, a5, a6, a7, b2, b3);
            }
        }
    }

    #pragma unroll
    for (int r = 0; r < 4; r++) {
        lv[r] += __shfl_xor_sync(0xffffffff, lv[r], 1);
        lv[r] += __shfl_xor_sync(0xffffffff, lv[r], 2);
    }

    const int ps = b * SPLITS + sp;
    if (tig == 0) {
        g_pl[ps * NN + j0] = lv[0];
        g_pl[ps * NN + j1] = lv[1];
        g_pl[ps * NN + j2] = lv[2];
        g_pl[ps * NN + j3] = lv[3];
    }
    #pragma unroll
    for (int nt = 0; nt < 8; nt++) {
        const int c = nt * 8 + 2 * tig;
        g_pacc[(ps * CC + c)     * NN + j0] = accA[nt * 4 + 0];
        g_pacc[(ps * CC + c + 1) * NN + j0] = accA[nt * 4 + 1];
        g_pacc[(ps * CC + c)     * NN + j1] = accA[nt * 4 + 2];
        g_pacc[(ps * CC + c + 1) * NN + j1] = accA[nt * 4 + 3];
        g_pacc[(ps * CC + c)     * NN + j2] = accB[nt * 4 + 0];
        g_pacc[(ps * CC + c + 1) * NN + j2] = accB[nt * 4 + 1];
        g_pacc[(ps * CC + c)     * NN + j3] = accB[nt * 4 + 2];
        g_pacc[(ps * CC + c + 1) * NN + j3] = accB[nt * 4 + 3];
    }
}

// ---------------------------------------------------------------------------
// Kernel 4: combine split partials (plain sums), residual. grid (72, 16).
// ---------------------------------------------------------------------------
__global__ __launch_bounds__(256)
void reduce_kernel(const float* __restrict__ x,
                   const float* __restrict__ gamma,
                   float* __restrict__ out) {
    const int t  = blockIdx.x * 256 + threadIdx.x;
    const int b  = t / NN;
    const int j  = t % NN;
    const int c0 = blockIdx.y * 4;

    float L = 0.f;
    #pragma unroll
    for (int s = 0; s < SPLITS; s++) L += g_pl[(b * SPLITS + s) * NN + j];
    const float inv = gamma[0] / L;

    #pragma unroll
    for (int c = c0; c < c0 + 4; c++) {
        float a = 0.f;
        #pragma unroll
        for (int s = 0; s < SPLITS; s++)
            a += g_pacc[((b * SPLITS + s) * CC + c) * NN + j];
        const int idx = (b * CC + c) * NN + j;
        out[idx] = a * inv + x[idx];
    }
}

// ---------------------------------------------------------------------------
extern "C" void kernel_launch(void* const* d_in, const int* in_sizes, int n_in,
                              void* d_out, int out_size) {
    const float* x     = (const float*)d_in[0];
    const float* Wq    = (const float*)d_in[1];
    const float* bq    = (const float*)d_in[2];
    const float* Wk    = (const float*)d_in[3];
    const float* bk    = (const float*)d_in[4];
    const float* Wv    = (const float*)d_in[5];
    const float* bv    = (const float*)d_in[6];
    const float* gamma = (const float*)d_in[7];
    float* out = (float*)d_out;

    static bool configured = false;
    if (!configured) {
        cudaFuncSetAttribute(attn_kernel,
                             cudaFuncAttributePreferredSharedMemoryCarveout,
                             cudaSharedmemCarveoutMaxShared);
        configured = true;
    }

    sigma_kernel<<<3, 64>>>(Wq, Wk, Wv);
    proj_kernel<<<(BB * NN) / 128, 128>>>(x, Wq, bq, Wk, bk, Wv, bv);
    attn_kernel<<<dim3(NN / 128, BB, SPLITS), 128>>>();
    reduce_kernel<<<dim3((BB * NN) / 256, 16), 256>>>(x, gamma, out);
}